// round 11
// baseline (speedup 1.0000x reference)
#include <cuda_runtime.h>
#include <cstdint>
#include <math.h>

#define D_DIM   1024
#define T_DIM   50
#define STRIDEQ 10
#define NUM_POS 16
#define MAX_B   4096
#define MAX_KP  13108   /* ceil(131072/10) */
#define NWMAX   416     /* ceil(13108/32)=410, padded */
#define AG      4       /* anchors per select block */

typedef unsigned long long ull;

// ---- device scratch (static; no allocations allowed) ----
__device__ ulonglong2 g_q[MAX_KP];
__device__ ulonglong2 g_a[MAX_B];
__device__ int        g_key[MAX_B];
__device__ int        g_order[MAX_B];
__device__ int        g_sel[MAX_B * NUM_POS];
__device__ int        g_cnt[MAX_B];
__device__ float      g_per[MAX_B];
__device__ unsigned   g_counter;

// ------------------------------------------------------------------
// Kernel 1: pack labels; anchors also get a density-proxy key.
// ------------------------------------------------------------------
__global__ void prep_labels(const int* __restrict__ xlab,
                            const int* __restrict__ qlab,
                            int B, int Kp) {
    if (blockIdx.x == 0 && threadIdx.x == 0) g_counter = 0;
    int warp = (blockIdx.x * blockDim.x + threadIdx.x) >> 5;
    int lane = threadIdx.x & 31;
    if (warp >= Kp + B) return;

    const int* lp = (warp < Kp)
        ? qlab + (long long)warp * STRIDEQ * (T_DIM * 2)
        : xlab + (long long)(warp - Kp) * (T_DIM * 2);

    int2 va = ((const int2*)lp)[lane];
    int l0b = 0, l1b = 0;
    if (32 + lane < T_DIM) {
        int2 vb = ((const int2*)lp)[32 + lane];
        l0b = vb.x; l1b = vb.y;
    }
    unsigned b0lo = __ballot_sync(0xffffffffu, va.x != 0);
    unsigned b1lo = __ballot_sync(0xffffffffu, va.y != 0);
    unsigned b0hi = __ballot_sync(0xffffffffu, l0b != 0);
    unsigned b1hi = __ballot_sync(0xffffffffu, l1b != 0);
    if (lane == 0) {
        ulonglong2 v;
        v.x = (ull)b0lo | ((ull)b0hi << 32);
        v.y = (ull)b1lo | ((ull)b1hi << 32);
        if (warp < Kp) g_q[warp] = v;
        else {
            int b = warp - Kp;
            g_a[b] = v;
            float mu = 0.4268f * (float)__popcll(v.x ^ v.y)
                     + 0.6036f * (float)__popcll(v.x & v.y);
            int key = (int)(mu * 8.0f);
            g_key[b] = key > 255 ? 255 : (key < 0 ? 0 : key);
        }
    }
}

// ------------------------------------------------------------------
// Kernel 2: counting sort of anchors by density key (single block).
// (Validated R6.)
// ------------------------------------------------------------------
__global__ void __launch_bounds__(256)
sort_anchors(int B) {
    __shared__ int hist[256];
    __shared__ int off[256];
    int tid = threadIdx.x;
    hist[tid] = 0;
    __syncthreads();
    for (int i = tid; i < B; i += 256) atomicAdd(&hist[g_key[i]], 1);
    __syncthreads();
    if (tid == 0) {
        int acc = 0;
        for (int i = 0; i < 256; i++) { off[i] = acc; acc += hist[i]; }
    }
    __syncthreads();
    for (int i = tid; i < B; i += 256) {
        int p = atomicAdd(&off[g_key[i]], 1);
        g_order[p] = i;
    }
}

// ------------------------------------------------------------------
// Cheap predicate (validated R9/R10: rel_err unchanged).
// ------------------------------------------------------------------
__device__ __forceinline__ bool pred_fast(
    ull q0, ull q1, ull a0, ull a1, ull da, ull xa, ull orA, float c) {
    ull mE = ~(q0 ^ a0) & ~(q1 ^ a1) & orA;
    ull mc = (da & (q0 ^ q1)) | (xa & (q0 & q1));
    float s = (float)__popcll(mE) + (float)__popcll(mc) * c;
    return s >= 25.0f;
}

// ------------------------------------------------------------------
// Kernel 3: grouped select. 512 threads, AG=4 density-matched anchors
// per block; each g_q load feeds 4 predicates (traffic /4); skip flag
// per satisfied anchor; chunk=512 early exit; per-warp extraction.
// ------------------------------------------------------------------
__global__ void __launch_bounds__(512)
select_grouped(int B, int Kp) {
    __shared__ unsigned s_words[AG][NWMAX];
    __shared__ int      s_tot[AG];
    int tid  = threadIdx.x;
    int lane = tid & 31;
    int w    = tid >> 5;
    int grp  = blockIdx.x * AG;

    int bidx[AG];
    ull a0[AG], a1[AG], da[AG], xa[AG], orA[AG];
#pragma unroll
    for (int j = 0; j < AG; j++) {
        int b = g_order[grp + j];
        bidx[j] = b;
        ulonglong2 av = g_a[b];
        a0[j] = av.x; a1[j] = av.y;
        da[j] = av.x & av.y; xa[j] = av.x ^ av.y; orA[j] = av.x | av.y;
    }
    float c = 1.0f / (sqrtf(2.0f) + 1e-8f);

    if (tid < AG) s_tot[tid] = 0;
    __syncthreads();

    bool done[AG] = {false, false, false, false};
    int scan_end = 0;
#pragma unroll 1
    for (int base = 0; base < Kp; base += 512) {
        int k = base + tid;
        bool inb = (k < Kp);
        ull q0 = 0, q1 = 0;
        if (inb) { ulonglong2 qv = g_q[k]; q0 = qv.x; q1 = qv.y; }
#pragma unroll
        for (int j = 0; j < AG; j++) {
            if (!done[j]) {
                bool pred = inb &&
                    pred_fast(q0, q1, a0[j], a1[j], da[j], xa[j], orA[j], c);
                unsigned m = __ballot_sync(0xffffffffu, pred);
                if (lane == 0) s_words[j][(base >> 5) + w] = m;
            }
        }
        __syncthreads();
        // warp j counts its anchor's 16 new words
        if (w < AG && !done[w]) {
            int w0 = base >> 5;
            int cw = (lane < 16) ? __popc(s_words[w][w0 + lane]) : 0;
#pragma unroll
            for (int o = 16; o; o >>= 1) cw += __shfl_xor_sync(0xffffffffu, cw, o);
            if (lane == 0) s_tot[w] += cw;
        }
        __syncthreads();
        scan_end = (base + 512 < Kp) ? base + 512 : Kp;
        bool all = true;
#pragma unroll
        for (int j = 0; j < AG; j++) {
            done[j] = (s_tot[j] >= NUM_POS);
            all &= done[j];
        }
        if (all) break;
    }

    // ---- ordered extraction: warp j extracts anchor j (validated) ----
    if (w < AG) {
        int b = bidx[w];
        int total = s_tot[w];
        int nwords = (scan_end + 31) >> 5;
        int run = 0;
        for (int g = 0; g * 32 < nwords && run < NUM_POS; g++) {
            int wi = g * 32 + lane;
            unsigned word = (wi < nwords) ? s_words[w][wi] : 0u;
            int my = __popc(word);
            int pre = my;
#pragma unroll
            for (int o = 1; o < 32; o <<= 1) {
                int v = __shfl_up_sync(0xffffffffu, pre, o);
                if (lane >= o) pre += v;
            }
            int gtot = __shfl_sync(0xffffffffu, pre, 31);
            int rank = run + pre - my;
            while (word && rank < NUM_POS) {
                int bit = __ffs(word) - 1;
                word &= word - 1;
                g_sel[b * NUM_POS + rank++] = wi * 32 + bit;
            }
            run += gtot;
        }
        if (lane == 0) g_cnt[b] = (total < NUM_POS) ? total : NUM_POS;
    }
}

// ------------------------------------------------------------------
// Kernel 4: per anchor, 16 gathered dots (norms fused) + loss +
// last-block deterministic mean. (Validated numeric path.)
// ------------------------------------------------------------------
__global__ void __launch_bounds__(512)
loss_kernel(const float* __restrict__ xq, const float* __restrict__ qf,
            float* __restrict__ out, int B) {
    __shared__ float4 s_anchor4[D_DIM / 4];   // 16B aligned
    __shared__ double s_red[512];
    __shared__ float  s_ssq[256];
    __shared__ float  s_loss[NUM_POS];
    __shared__ int    s_last;

    int b    = blockIdx.x;
    int tid  = threadIdx.x;
    int w    = tid >> 5;
    int lane = tid & 31;

    if (tid >= 256) {
        int i = tid - 256;
        float4 v = ((const float4*)(xq + (long long)b * D_DIM))[i];
        s_anchor4[i] = v;
        s_ssq[i] = v.x * v.x + v.y * v.y + v.z * v.z + v.w * v.w;
    }
    __syncthreads();

    int cnt = g_cnt[b];
    float loss = 0.f;
    if (w < cnt) {
        int kp = g_sel[b * NUM_POS + w];
        const float4* pk = (const float4*)(qf + (long long)kp * STRIDEQ * D_DIM);
        const float4* pa = (const float4*)s_anchor4;
        float dot = 0.f, kss = 0.f;
#pragma unroll
        for (int i = 0; i < D_DIM / 4 / 32; i++) {
            float4 a  = pa[lane + i * 32];
            float4 kk = pk[lane + i * 32];
            dot += a.x * kk.x + a.y * kk.y + a.z * kk.z + a.w * kk.w;
            kss += kk.x * kk.x + kk.y * kk.y + kk.z * kk.z + kk.w * kk.w;
        }
#pragma unroll
        for (int o = 16; o; o >>= 1) {
            dot += __shfl_xor_sync(0xffffffffu, dot, o);
            kss += __shfl_xor_sync(0xffffffffu, kss, o);
        }
        float qss = s_ssq[lane] + s_ssq[lane + 32] + s_ssq[lane + 64]
                  + s_ssq[lane + 96] + s_ssq[lane + 128] + s_ssq[lane + 160]
                  + s_ssq[lane + 192] + s_ssq[lane + 224];
#pragma unroll
        for (int o = 16; o; o >>= 1) qss += __shfl_xor_sync(0xffffffffu, qss, o);

        float inv_q = 1.0f / (sqrtf(qss) + 1e-8f);
        float inv_k = 1.0f / (sqrtf(kss) + 1e-8f);
        float s = dot * inv_q * inv_k * 2.0f;     // / TEMPERATURE(0.5)
        float z = -s;                              // -log_sigmoid(s)
        loss = fmaxf(z, 0.f) + log1pf(expf(-fabsf(z)));
    }
    if (lane == 0 && w < NUM_POS) s_loss[w] = loss;
    __syncthreads();

    if (tid == 0) {
        float sum = 0.f;
#pragma unroll
        for (int i = 0; i < NUM_POS; i++) sum += (i < cnt) ? s_loss[i] : 0.f;
        g_per[b] = (cnt > 0) ? (sum / (float)cnt) : 0.f;
        __threadfence();
        unsigned t = atomicAdd(&g_counter, 1u);
        s_last = (t == (unsigned)(gridDim.x - 1)) ? 1 : 0;
    }
    __syncthreads();

    if (s_last) {
        double acc = 0.0;
        for (int i = tid; i < B; i += 512) acc += (double)g_per[i];
        s_red[tid] = acc;
        __syncthreads();
        for (int s = 256; s; s >>= 1) {
            if (tid < s) s_red[tid] += s_red[tid + s];
            __syncthreads();
        }
        if (tid == 0) out[0] = (float)(s_red[0] / (double)B);
    }
}

extern "C" void kernel_launch(void* const* d_in, const int* in_sizes, int n_in,
                              void* d_out, int out_size) {
    const float* xq   = (const float*)d_in[0];
    const int*   xlab = (const int*)  d_in[1];
    const float* qf   = (const float*)d_in[2];
    const int*   qlab = (const int*)  d_in[3];

    int B  = in_sizes[0] / D_DIM;                 // 4096
    int K  = in_sizes[2] / D_DIM;                 // 131072
    int Kp = (K + STRIDEQ - 1) / STRIDEQ;         // 13108

    int warps  = Kp + B;
    int blocks = (warps * 32 + 255) / 256;
    prep_labels   <<<blocks, 256>>>(xlab, qlab, B, Kp);
    sort_anchors  <<<1, 256>>>(B);
    select_grouped<<<B / AG, 512>>>(B, Kp);
    loss_kernel   <<<B, 512>>>(xq, qf, (float*)d_out, B);
}

// round 12
// speedup vs baseline: 1.0384x; 1.0384x over previous
#include <cuda_runtime.h>
#include <cstdint>
#include <math.h>

#define D_DIM   1024
#define T_DIM   50
#define STRIDEQ 10
#define NUM_POS 16
#define MAX_B   4096
#define MAX_KP  13108   /* ceil(131072/10) */
#define NWMAX   416     /* ceil(13108/32)=410, padded */

typedef unsigned long long ull;

// ---- device scratch (static; no allocations allowed) ----
__device__ ulonglong2 g_q[MAX_KP];
__device__ ulonglong2 g_a[MAX_B];
__device__ int        g_sel[MAX_B * NUM_POS];
__device__ int        g_cnt[MAX_B];
__device__ float      g_per[MAX_B];
__device__ unsigned   g_counter;

// ------------------------------------------------------------------
// Kernel 1: pack labels (strided queue rows + anchors). Warp per row.
// ------------------------------------------------------------------
__global__ void prep_labels(const int* __restrict__ xlab,
                            const int* __restrict__ qlab,
                            int B, int Kp) {
    if (blockIdx.x == 0 && threadIdx.x == 0) g_counter = 0;
    int warp = (blockIdx.x * blockDim.x + threadIdx.x) >> 5;
    int lane = threadIdx.x & 31;
    if (warp >= Kp + B) return;

    const int* lp = (warp < Kp)
        ? qlab + (long long)warp * STRIDEQ * (T_DIM * 2)
        : xlab + (long long)(warp - Kp) * (T_DIM * 2);

    int2 va = ((const int2*)lp)[lane];
    int l0b = 0, l1b = 0;
    if (32 + lane < T_DIM) {
        int2 vb = ((const int2*)lp)[32 + lane];
        l0b = vb.x; l1b = vb.y;
    }
    unsigned b0lo = __ballot_sync(0xffffffffu, va.x != 0);
    unsigned b1lo = __ballot_sync(0xffffffffu, va.y != 0);
    unsigned b0hi = __ballot_sync(0xffffffffu, l0b != 0);
    unsigned b1hi = __ballot_sync(0xffffffffu, l1b != 0);
    if (lane == 0) {
        ulonglong2 v;
        v.x = (ull)b0lo | ((ull)b0hi << 32);
        v.y = (ull)b1lo | ((ull)b1hi << 32);
        if (warp < Kp) g_q[warp]      = v;
        else           g_a[warp - Kp] = v;
    }
}

// ------------------------------------------------------------------
// Cheap predicate (validated R9-R11: rel_err unchanged).
// ------------------------------------------------------------------
__device__ __forceinline__ bool pred_fast(
    ull q0, ull q1, ull a0, ull a1, ull da, ull xa, ull orA, float c) {
    ull mE = ~(q0 ^ a0) & ~(q1 ^ a1) & orA;
    ull mc = (da & (q0 ^ q1)) | (xa & (q0 & q1));
    float s = (float)__popcll(mE) + (float)__popcll(mc) * c;
    return s >= 25.0f;
}

// ------------------------------------------------------------------
// Kernel 2: block-per-anchor select, software-pipelined.
// 256 threads (8 blocks/SM -> 2x chains of R10). Each chunk = 512
// evals (2/thread); next chunk's loads issued BEFORE this chunk's
// barriers so LDG latency hides behind them. Exit granularity 256.
// ------------------------------------------------------------------
__global__ void __launch_bounds__(256)
select_block(int B, int Kp) {
    __shared__ unsigned s_words[NWMAX];
    int b    = blockIdx.x;
    int tid  = threadIdx.x;
    int w    = tid >> 5;
    int lane = tid & 31;

    ulonglong2 av = g_a[b];
    ull a0 = av.x, a1 = av.y;
    ull da = a0 & a1, xa = a0 ^ a1, orA = a0 | a1;
    float c = 1.0f / (sqrtf(2.0f) + 1e-8f);

    // prefetch chunk 0
    int k0 = tid;
    int k1 = 256 + tid;
    ulonglong2 cur0 = g_q[k0 < Kp ? k0 : (Kp - 1)];
    ulonglong2 cur1 = g_q[k1 < Kp ? k1 : (Kp - 1)];

    int total    = 0;
    int scan_end = 0;
#pragma unroll 1
    for (int base = 0; base < Kp; base += 512) {
        int ka = base + tid;
        int kb = base + 256 + tid;
        bool p0 = (ka < Kp) && pred_fast(cur0.x, cur0.y, a0, a1, da, xa, orA, c);
        bool p1 = (kb < Kp) && pred_fast(cur1.x, cur1.y, a0, a1, da, xa, orA, c);
        unsigned m0 = __ballot_sync(0xffffffffu, p0);
        unsigned m1 = __ballot_sync(0xffffffffu, p1);
        if (lane == 0) {
            s_words[(base >> 5) + w]     = m0;
            s_words[(base >> 5) + 8 + w] = m1;
        }
        // prefetch next chunk before the barriers (latency hidden)
        int na = base + 512 + tid;
        int nb = base + 768 + tid;
        ulonglong2 nxt0 = g_q[na < Kp ? na : (Kp - 1)];
        ulonglong2 nxt1 = g_q[nb < Kp ? nb : (Kp - 1)];

        total += __syncthreads_count(p0);            // barrier + count
        scan_end = (base + 256 < Kp) ? base + 256 : Kp;
        if (total >= NUM_POS) break;

        total += __syncthreads_count(p1);
        scan_end = (base + 512 < Kp) ? base + 512 : Kp;
        if (total >= NUM_POS) break;

        cur0 = nxt0;
        cur1 = nxt1;
    }

    // ---- ordered extraction of first <=16 hits (warp 0, validated) ----
    if (w == 0) {
        int nwords = (scan_end + 31) >> 5;
        int run = 0;
        for (int g = 0; g * 32 < nwords && run < NUM_POS; g++) {
            int wi = g * 32 + lane;
            unsigned word = (wi < nwords) ? s_words[wi] : 0u;
            int my = __popc(word);
            int pre = my;
#pragma unroll
            for (int o = 1; o < 32; o <<= 1) {
                int v = __shfl_up_sync(0xffffffffu, pre, o);
                if (lane >= o) pre += v;
            }
            int gtot = __shfl_sync(0xffffffffu, pre, 31);
            int rank = run + pre - my;
            while (word && rank < NUM_POS) {
                int bit = __ffs(word) - 1;
                word &= word - 1;
                g_sel[b * NUM_POS + rank++] = wi * 32 + bit;
            }
            run += gtot;
        }
        if (lane == 0) g_cnt[b] = (total < NUM_POS) ? total : NUM_POS;
    }
}

// ------------------------------------------------------------------
// Kernel 3: per anchor, 16 gathered dots (norms fused) + loss +
// last-block deterministic mean. (Validated numeric path.)
// ------------------------------------------------------------------
__global__ void __launch_bounds__(512)
loss_kernel(const float* __restrict__ xq, const float* __restrict__ qf,
            float* __restrict__ out, int B) {
    __shared__ float4 s_anchor4[D_DIM / 4];   // 16B aligned
    __shared__ double s_red[512];
    __shared__ float  s_ssq[256];
    __shared__ float  s_loss[NUM_POS];
    __shared__ int    s_last;

    int b    = blockIdx.x;
    int tid  = threadIdx.x;
    int w    = tid >> 5;
    int lane = tid & 31;

    if (tid >= 256) {
        int i = tid - 256;
        float4 v = ((const float4*)(xq + (long long)b * D_DIM))[i];
        s_anchor4[i] = v;
        s_ssq[i] = v.x * v.x + v.y * v.y + v.z * v.z + v.w * v.w;
    }
    __syncthreads();

    int cnt = g_cnt[b];
    float loss = 0.f;
    if (w < cnt) {
        int kp = g_sel[b * NUM_POS + w];
        const float4* pk = (const float4*)(qf + (long long)kp * STRIDEQ * D_DIM);
        const float4* pa = (const float4*)s_anchor4;
        float dot = 0.f, kss = 0.f;
#pragma unroll
        for (int i = 0; i < D_DIM / 4 / 32; i++) {
            float4 a  = pa[lane + i * 32];
            float4 kk = pk[lane + i * 32];
            dot += a.x * kk.x + a.y * kk.y + a.z * kk.z + a.w * kk.w;
            kss += kk.x * kk.x + kk.y * kk.y + kk.z * kk.z + kk.w * kk.w;
        }
#pragma unroll
        for (int o = 16; o; o >>= 1) {
            dot += __shfl_xor_sync(0xffffffffu, dot, o);
            kss += __shfl_xor_sync(0xffffffffu, kss, o);
        }
        float qss = s_ssq[lane] + s_ssq[lane + 32] + s_ssq[lane + 64]
                  + s_ssq[lane + 96] + s_ssq[lane + 128] + s_ssq[lane + 160]
                  + s_ssq[lane + 192] + s_ssq[lane + 224];
#pragma unroll
        for (int o = 16; o; o >>= 1) qss += __shfl_xor_sync(0xffffffffu, qss, o);

        float inv_q = 1.0f / (sqrtf(qss) + 1e-8f);
        float inv_k = 1.0f / (sqrtf(kss) + 1e-8f);
        float s = dot * inv_q * inv_k * 2.0f;     // / TEMPERATURE(0.5)
        float z = -s;                              // -log_sigmoid(s)
        loss = fmaxf(z, 0.f) + log1pf(expf(-fabsf(z)));
    }
    if (lane == 0 && w < NUM_POS) s_loss[w] = loss;
    __syncthreads();

    if (tid == 0) {
        float sum = 0.f;
#pragma unroll
        for (int i = 0; i < NUM_POS; i++) sum += (i < cnt) ? s_loss[i] : 0.f;
        g_per[b] = (cnt > 0) ? (sum / (float)cnt) : 0.f;
        __threadfence();
        unsigned t = atomicAdd(&g_counter, 1u);
        s_last = (t == (unsigned)(gridDim.x - 1)) ? 1 : 0;
    }
    __syncthreads();

    if (s_last) {
        double acc = 0.0;
        for (int i = tid; i < B; i += 512) acc += (double)g_per[i];
        s_red[tid] = acc;
        __syncthreads();
        for (int s = 256; s; s >>= 1) {
            if (tid < s) s_red[tid] += s_red[tid + s];
            __syncthreads();
        }
        if (tid == 0) out[0] = (float)(s_red[0] / (double)B);
    }
}

extern "C" void kernel_launch(void* const* d_in, const int* in_sizes, int n_in,
                              void* d_out, int out_size) {
    const float* xq   = (const float*)d_in[0];
    const int*   xlab = (const int*)  d_in[1];
    const float* qf   = (const float*)d_in[2];
    const int*   qlab = (const int*)  d_in[3];

    int B  = in_sizes[0] / D_DIM;                 // 4096
    int K  = in_sizes[2] / D_DIM;                 // 131072
    int Kp = (K + STRIDEQ - 1) / STRIDEQ;         // 13108

    int warps  = Kp + B;
    int blocks = (warps * 32 + 255) / 256;
    prep_labels <<<blocks, 256>>>(xlab, qlab, B, Kp);
    select_block<<<B, 256>>>(B, Kp);
    loss_kernel <<<B, 512>>>(xq, qf, (float*)d_out, B);
}

// round 13
// speedup vs baseline: 1.0817x; 1.0418x over previous
#include <cuda_runtime.h>
#include <cstdint>
#include <math.h>

#define D_DIM   1024
#define T_DIM   50
#define STRIDEQ 10
#define NUM_POS 16
#define MAX_B   4096
#define MAX_KP  13108   /* ceil(131072/10) */
#define NWMAX   416     /* ceil(13108/32)=410, padded */

typedef unsigned long long ull;

// ---- device scratch (static; no allocations allowed) ----
__device__ ulonglong2 g_q[MAX_KP];    // (q0, q1)
__device__ ulonglong2 g_qd[MAX_KP];   // (dq = q0&q1, xq = q0^q1)
__device__ ulonglong2 g_a[MAX_B];
__device__ int        g_sel[MAX_B * NUM_POS];
__device__ int        g_cnt[MAX_B];
__device__ float      g_per[MAX_B];
__device__ unsigned   g_counter;

// ------------------------------------------------------------------
// Kernel 1: pack labels (strided queue rows + anchors). Warp per row.
// Queue rows also get precomputed (dq, xq).
// ------------------------------------------------------------------
__global__ void prep_labels(const int* __restrict__ xlab,
                            const int* __restrict__ qlab,
                            int B, int Kp) {
    if (blockIdx.x == 0 && threadIdx.x == 0) g_counter = 0;
    int warp = (blockIdx.x * blockDim.x + threadIdx.x) >> 5;
    int lane = threadIdx.x & 31;
    if (warp >= Kp + B) return;

    const int* lp = (warp < Kp)
        ? qlab + (long long)warp * STRIDEQ * (T_DIM * 2)
        : xlab + (long long)(warp - Kp) * (T_DIM * 2);

    int2 va = ((const int2*)lp)[lane];
    int l0b = 0, l1b = 0;
    if (32 + lane < T_DIM) {
        int2 vb = ((const int2*)lp)[32 + lane];
        l0b = vb.x; l1b = vb.y;
    }
    unsigned b0lo = __ballot_sync(0xffffffffu, va.x != 0);
    unsigned b1lo = __ballot_sync(0xffffffffu, va.y != 0);
    unsigned b0hi = __ballot_sync(0xffffffffu, l0b != 0);
    unsigned b1hi = __ballot_sync(0xffffffffu, l1b != 0);
    if (lane == 0) {
        ull v0 = (ull)b0lo | ((ull)b0hi << 32);
        ull v1 = (ull)b1lo | ((ull)b1hi << 32);
        if (warp < Kp) {
            g_q[warp]  = make_ulonglong2(v0, v1);
            g_qd[warp] = make_ulonglong2(v0 & v1, v0 ^ v1);
        } else {
            g_a[warp - Kp] = make_ulonglong2(v0, v1);
        }
    }
}

// ------------------------------------------------------------------
// Kernel 2: block-per-anchor select (R10 structure, validated best).
// Integer threshold table: pred = nc >= T[nE], T built with the SAME
// fp32 expression as the reference -> bit-exact by monotonicity.
// ------------------------------------------------------------------
__global__ void __launch_bounds__(512)
select_block(int B, int Kp) {
    __shared__ unsigned s_words[NWMAX];
    __shared__ int      s_T[64];          // threshold table, idx by nE
    int b    = blockIdx.x;
    int tid  = threadIdx.x;
    int w    = tid >> 5;
    int lane = tid & 31;

    float c = 1.0f / (sqrtf(2.0f) + 1e-8f);

    // build threshold table: T[nE] = min nc with (float)nE + nc*c >= 25
    if (tid < 64) {
        int nE = tid;
        int t;
        if ((float)nE >= 25.0f) t = 0;
        else {
            t = (int)((25.0f - (float)nE) / c) - 2;
            if (t < 0) t = 0;
            while ((float)nE + (float)t * c < 25.0f) t++;
        }
        s_T[tid] = t;
    }

    ulonglong2 av = g_a[b];
    ull a0 = av.x, a1 = av.y;
    ull da = a0 & a1, xa = a0 ^ a1, orA = a0 | a1;
    __syncthreads();

    int total    = 0;
    int scan_end = 0;
#pragma unroll 1
    for (int base = 0; base < Kp; base += 512) {
        int k = base + tid;
        bool pred = false;
        if (k < Kp) {
            ulonglong2 qv = g_q[k];
            ulonglong2 qd = g_qd[k];
            ull X  = qv.x ^ a0;
            ull Y  = qv.y ^ a1;
            ull mE = ~X & ~Y & orA;
            ull mc = (da & qd.y) | (xa & qd.x);
            int nE = __popcll(mE);
            int nc = __popcll(mc);
            pred = (nc >= s_T[nE]);
        }
        unsigned m = __ballot_sync(0xffffffffu, pred);
        if (lane == 0) s_words[(base >> 5) + w] = m;
        total += __syncthreads_count(pred);   // barrier + exact count
        scan_end = (base + 512 < Kp) ? base + 512 : Kp;
        if (total >= NUM_POS) break;
    }

    // ---- ordered extraction of first <=16 hits (warp 0, validated) ----
    if (w == 0) {
        int nwords = (scan_end + 31) >> 5;
        int run = 0;
        for (int g = 0; g * 32 < nwords && run < NUM_POS; g++) {
            int wi = g * 32 + lane;
            unsigned word = (wi < nwords) ? s_words[wi] : 0u;
            int my = __popc(word);
            int pre = my;
#pragma unroll
            for (int o = 1; o < 32; o <<= 1) {
                int v = __shfl_up_sync(0xffffffffu, pre, o);
                if (lane >= o) pre += v;
            }
            int gtot = __shfl_sync(0xffffffffu, pre, 31);
            int rank = run + pre - my;
            while (word && rank < NUM_POS) {
                int bit = __ffs(word) - 1;
                word &= word - 1;
                g_sel[b * NUM_POS + rank++] = wi * 32 + bit;
            }
            run += gtot;
        }
        if (lane == 0) g_cnt[b] = (total < NUM_POS) ? total : NUM_POS;
    }
}

// ------------------------------------------------------------------
// Kernel 3: per anchor, 16 gathered dots (norms fused) + loss +
// last-block deterministic mean. launch_bounds(512,4) -> occ ~100%.
// ------------------------------------------------------------------
__global__ void __launch_bounds__(512, 4)
loss_kernel(const float* __restrict__ xq, const float* __restrict__ qf,
            float* __restrict__ out, int B) {
    __shared__ float4 s_anchor4[D_DIM / 4];   // 16B aligned
    __shared__ double s_red[512];
    __shared__ float  s_ssq[256];
    __shared__ float  s_loss[NUM_POS];
    __shared__ int    s_last;

    int b    = blockIdx.x;
    int tid  = threadIdx.x;
    int w    = tid >> 5;
    int lane = tid & 31;

    if (tid >= 256) {
        int i = tid - 256;
        float4 v = ((const float4*)(xq + (long long)b * D_DIM))[i];
        s_anchor4[i] = v;
        s_ssq[i] = v.x * v.x + v.y * v.y + v.z * v.z + v.w * v.w;
    }
    __syncthreads();

    int cnt = g_cnt[b];
    float loss = 0.f;
    if (w < cnt) {
        int kp = g_sel[b * NUM_POS + w];
        const float4* pk = (const float4*)(qf + (long long)kp * STRIDEQ * D_DIM);
        const float4* pa = (const float4*)s_anchor4;
        float dot = 0.f, kss = 0.f;
#pragma unroll
        for (int i = 0; i < D_DIM / 4 / 32; i++) {
            float4 a  = pa[lane + i * 32];
            float4 kk = pk[lane + i * 32];
            dot += a.x * kk.x + a.y * kk.y + a.z * kk.z + a.w * kk.w;
            kss += kk.x * kk.x + kk.y * kk.y + kk.z * kk.z + kk.w * kk.w;
        }
#pragma unroll
        for (int o = 16; o; o >>= 1) {
            dot += __shfl_xor_sync(0xffffffffu, dot, o);
            kss += __shfl_xor_sync(0xffffffffu, kss, o);
        }
        float qss = s_ssq[lane] + s_ssq[lane + 32] + s_ssq[lane + 64]
                  + s_ssq[lane + 96] + s_ssq[lane + 128] + s_ssq[lane + 160]
                  + s_ssq[lane + 192] + s_ssq[lane + 224];
#pragma unroll
        for (int o = 16; o; o >>= 1) qss += __shfl_xor_sync(0xffffffffu, qss, o);

        float inv_q = 1.0f / (sqrtf(qss) + 1e-8f);
        float inv_k = 1.0f / (sqrtf(kss) + 1e-8f);
        float s = dot * inv_q * inv_k * 2.0f;     // / TEMPERATURE(0.5)
        float z = -s;                              // -log_sigmoid(s)
        loss = fmaxf(z, 0.f) + log1pf(expf(-fabsf(z)));
    }
    if (lane == 0 && w < NUM_POS) s_loss[w] = loss;
    __syncthreads();

    if (tid == 0) {
        float sum = 0.f;
#pragma unroll
        for (int i = 0; i < NUM_POS; i++) sum += (i < cnt) ? s_loss[i] : 0.f;
        g_per[b] = (cnt > 0) ? (sum / (float)cnt) : 0.f;
        __threadfence();
        unsigned t = atomicAdd(&g_counter, 1u);
        s_last = (t == (unsigned)(gridDim.x - 1)) ? 1 : 0;
    }
    __syncthreads();

    if (s_last) {
        double acc = 0.0;
        for (int i = tid; i < B; i += 512) acc += (double)g_per[i];
        s_red[tid] = acc;
        __syncthreads();
        for (int s = 256; s; s >>= 1) {
            if (tid < s) s_red[tid] += s_red[tid + s];
            __syncthreads();
        }
        if (tid == 0) out[0] = (float)(s_red[0] / (double)B);
    }
}

extern "C" void kernel_launch(void* const* d_in, const int* in_sizes, int n_in,
                              void* d_out, int out_size) {
    const float* xq   = (const float*)d_in[0];
    const int*   xlab = (const int*)  d_in[1];
    const float* qf   = (const float*)d_in[2];
    const int*   qlab = (const int*)  d_in[3];

    int B  = in_sizes[0] / D_DIM;                 // 4096
    int K  = in_sizes[2] / D_DIM;                 // 131072
    int Kp = (K + STRIDEQ - 1) / STRIDEQ;         // 13108

    int warps  = Kp + B;
    int blocks = (warps * 32 + 255) / 256;
    prep_labels <<<blocks, 256>>>(xlab, qlab, B, Kp);
    select_block<<<B, 512>>>(B, Kp);
    loss_kernel <<<B, 512>>>(xq, qf, (float*)d_out, B);
}